// round 14
// baseline (speedup 1.0000x reference)
#include <cuda_runtime.h>
#include <cuda_bf16.h>
#include <math.h>
#include <stdint.h>

#define BSZ 2
#define SEQ 2048
#define NH 16
#define DKV 64
#define DMODEL 1024
#define INNER 1024
#define MTOT (BSZ * SEQ)   // 4096
#define NHSD (BSZ * NH * SEQ * DKV)   // 4194304

// ---------------- scratch (static device memory; no allocations) ----------------
__device__ float g_bias[NH * 4096];
__device__ float g_maskf[BSZ * SEQ];
__device__ float2 g_stats[BSZ * NH * SEQ];             // per-row (max, 1/sum)
__device__ __nv_bfloat16 g_xhi[MTOT * DMODEL];
__device__ __nv_bfloat16 g_xlo[MTOT * DMODEL];
__device__ __nv_bfloat16 g_whi[4u * DMODEL * INNER];   // [n][k]; 0=Wq 1=Wk 2=Wv 3=Wo (contiguous)
__device__ __nv_bfloat16 g_wlo[4u * DMODEL * INNER];
__device__ __nv_bfloat16 g_qkvhi[2 * NHSD];            // Q then K  (b,h,s,d)
__device__ __nv_bfloat16 g_qkvlo[2 * NHSD];
__device__ __nv_bfloat16 g_vthi[NHSD];                 // V transposed (b,h,d,s)
__device__ __nv_bfloat16 g_vtlo[NHSD];
__device__ __nv_bfloat16 g_chi[MTOT * INNER];          // (b,s,inner)
__device__ __nv_bfloat16 g_clo[MTOT * INNER];

// ---------------- PTX helpers ----------------
__device__ __forceinline__ uint32_t smem_u32(const void* p) {
    uint32_t a;
    asm("{ .reg .u64 t; cvta.to.shared.u64 t, %1; cvt.u32.u64 %0, t; }" : "=r"(a) : "l"(p));
    return a;
}
#define LDSM_X4(r0, r1, r2, r3, addr) \
    asm volatile("ldmatrix.sync.aligned.m8n8.x4.shared.b16 {%0,%1,%2,%3}, [%4];" \
                 : "=r"(r0), "=r"(r1), "=r"(r2), "=r"(r3) : "r"(addr))
#define LDSM_X2(r0, r1, addr) \
    asm volatile("ldmatrix.sync.aligned.m8n8.x2.shared.b16 {%0,%1}, [%2];" \
                 : "=r"(r0), "=r"(r1) : "r"(addr))
#define CP_ASYNC16(dst, src) \
    asm volatile("cp.async.cg.shared.global [%0], [%1], 16;" :: "r"(dst), "l"(src))
#define CP_COMMIT() asm volatile("cp.async.commit_group;" ::: "memory")
#define CP_WAIT0()  asm volatile("cp.async.wait_group 0;" ::: "memory")
#define CP_WAIT1()  asm volatile("cp.async.wait_group 1;" ::: "memory")
#define CP_WAIT2()  asm volatile("cp.async.wait_group 2;" ::: "memory")

__device__ __forceinline__ void mma16816(float* c, const uint32_t* a, const uint32_t* b) {
    asm volatile("mma.sync.aligned.m16n8k16.row.col.f32.bf16.bf16.f32 "
                 "{%0,%1,%2,%3}, {%4,%5,%6,%7}, {%8,%9}, {%0,%1,%2,%3};"
                 : "+f"(c[0]), "+f"(c[1]), "+f"(c[2]), "+f"(c[3])
                 : "r"(a[0]), "r"(a[1]), "r"(a[2]), "r"(a[3]), "r"(b[0]), "r"(b[1]));
}

__device__ __forceinline__ void split2(float v0, float v1, uint32_t& hi, uint32_t& lo) {
    __nv_bfloat16 h0 = __float2bfloat16(v0), h1 = __float2bfloat16(v1);
    __nv_bfloat16 l0 = __float2bfloat16(v0 - __bfloat162float(h0));
    __nv_bfloat16 l1 = __float2bfloat16(v1 - __bfloat162float(h1));
    hi = (uint32_t)__bfloat16_as_ushort(h0) | ((uint32_t)__bfloat16_as_ushort(h1) << 16);
    lo = (uint32_t)__bfloat16_as_ushort(l0) | ((uint32_t)__bfloat16_as_ushort(l1) << 16);
}
__device__ __forceinline__ void split1(float v, __nv_bfloat16& h, __nv_bfloat16& l) {
    h = __float2bfloat16(v);
    l = __float2bfloat16(v - __bfloat162float(h));
}

// ---------------- T5 relative-position bucket ----------------
__device__ __forceinline__ int rel_bucket(int delta) {
    int ret = (delta > 0) ? 32 : 0;
    int n = (delta < 0) ? -delta : delta;
    if (n < 16) return ret + n;
    float t = logf((float)n / 16.0f);
    t = t / 1.1394342831883648f;
    t = t * 16.0f;
    int large = 16 + (int)t;
    if (large > 31) large = 31;
    return ret + large;
}

// ---------------- combined prep: cvt | weight transpose | biasfill | maskprep ----------------
#define NCVT 4096           // (MTOT*DMODEL)/1024
#define NTRANS 4096         // 32*32*4
__global__ void prep_kernel(const float* __restrict__ x,
                            const float* __restrict__ w0, const float* __restrict__ w1,
                            const float* __restrict__ w2, const float* __restrict__ w3,
                            const float* __restrict__ rel_table,
                            const unsigned char* __restrict__ mraw) {
    const int blk = blockIdx.x;
    const int tid = threadIdx.x;
    if (blk < NCVT) {
        size_t i = ((size_t)blk * 256 + tid) * 4;
        float4 v = *(const float4*)(x + i);
        uint2 H, L;
        split2(v.x, v.y, H.x, L.x);
        split2(v.z, v.w, H.y, L.y);
        *(uint2*)(g_xhi + i) = H;
        *(uint2*)(g_xlo + i) = L;
    } else if (blk < NCVT + NTRANS) {
        __shared__ float t[32][33];
        int b2 = blk - NCVT;
        int z = b2 >> 10, rem = b2 & 1023;
        const float* src = (z == 0) ? w0 : (z == 1) ? w1 : (z == 2) ? w2 : w3;
        __nv_bfloat16* dhi = g_whi + (size_t)z * DMODEL * INNER;
        __nv_bfloat16* dlo = g_wlo + (size_t)z * DMODEL * INNER;
        int tx = tid & 31, ty = tid >> 5;
        int n0 = (rem & 31) * 32, k0 = (rem >> 5) * 32;
#pragma unroll
        for (int j = 0; j < 32; j += 8)
            t[ty + j][tx] = src[(size_t)(k0 + ty + j) * INNER + n0 + tx];
        __syncthreads();
#pragma unroll
        for (int j = 0; j < 32; j += 8) {
            float v = t[tx][ty + j];
            int n = n0 + ty + j, k = k0 + tx;
            __nv_bfloat16 h = __float2bfloat16(v);
            dhi[(size_t)n * DMODEL + k] = h;
            dlo[(size_t)n * DMODEL + k] = __float2bfloat16(v - __bfloat162float(h));
        }
    } else if (blk < NCVT + NTRANS + 256) {
        int idx = (blk - NCVT - NTRANS) * 256 + tid;     // NH*4096 = 65536
        int h = idx >> 12;
        int dd = idx & 4095;
        int delta = dd - (SEQ - 1);
        if (dd >= 2 * SEQ - 1) delta = 0;
        g_bias[idx] = rel_table[rel_bucket(delta) * NH + h];
    } else {
        // mask prep (bool stored as int32 or u8 — detect)
        __shared__ int s_nonzero;
        if (tid == 0) s_nonzero = 0;
        __syncthreads();
        int cnt = 0;
        for (int i = tid; i < BSZ * SEQ; i += 256)
            if ((i & 3) && mraw[i]) cnt++;
        if (cnt) atomicAdd(&s_nonzero, cnt);
        __syncthreads();
        const bool is_u8 = (s_nonzero > 0);
        const int* mi = (const int*)mraw;
        for (int i = tid; i < BSZ * SEQ; i += 256) {
            int flag = is_u8 ? (int)mraw[i] : mi[i];
            g_maskf[i] = flag ? -INFINITY : 0.0f;
        }
    }
}

// ---------------- pos_bias output (1,h,q,k) ----------------
__global__ void posbias_kernel(float* __restrict__ pb) {
    size_t idx = (size_t)blockIdx.x * 256 + threadIdx.x;   // NH*SEQ*SEQ
    int k = (int)(idx & (SEQ - 1));
    int q = (int)((idx >> 11) & (SEQ - 1));
    int h = (int)(idx >> 22);
    pb[idx] = g_bias[(h << 12) + (k - q + SEQ - 1)];
}

// ---------------- 3-stage pipelined mma.sync GEMM ----------------
#define APAD 40
#define GA_ELE (2 * 128 * APAD)
#define GB_ELE (2 * 64 * APAD)
#define GEMM_SMEM ((3 * (GA_ELE + GB_ELE)) * 2)

__global__ __launch_bounds__(256) void mma_gemm_kernel(
    const __nv_bfloat16* __restrict__ Ahi, const __nv_bfloat16* __restrict__ Alo,
    const __nv_bfloat16* __restrict__ Bhi, const __nv_bfloat16* __restrict__ Blo,
    const float* __restrict__ bias0, const float* __restrict__ bias1,
    const float* __restrict__ bias2, float* __restrict__ C, int mode)
{
    extern __shared__ char gsm_raw[];
    __nv_bfloat16* sA = (__nv_bfloat16*)gsm_raw;
    __nv_bfloat16* sB = sA + 3 * GA_ELE;

    const int tid = threadIdx.x;
    const int wid = tid >> 5, lane = tid & 31;
    const int m0 = blockIdx.y * 128;
    const int n0b = blockIdx.x * 64;
    const int mw = (wid & 3) * 32;
    const int nw = (wid >> 2) * 32;

    float acc[2][4][4];
#pragma unroll
    for (int mt = 0; mt < 2; mt++)
#pragma unroll
        for (int nt = 0; nt < 4; nt++)
#pragma unroll
            for (int i = 0; i < 4; i++) acc[mt][nt][i] = 0.f;

    const int arow = lane & 15;
    const int acol0 = (lane >> 4) << 3;
    const int brow = lane & 7;
    const int bcol0 = ((lane >> 3) & 1) << 3;

    auto load_stage = [&](int st, int k0) {
#pragma unroll
        for (int h = 0; h < 2; h++) {
            const __nv_bfloat16* as = h ? Alo : Ahi;
#pragma unroll
            for (int it = 0; it < 2; it++) {
                int idx = tid + it * 256;
                int r = idx >> 2, seg = idx & 3;
                uint32_t dst = smem_u32(sA + ((st * 2 + h) * 128 + r) * APAD + seg * 8);
                CP_ASYNC16(dst, as + (size_t)(m0 + r) * 1024 + k0 + seg * 8);
            }
            const __nv_bfloat16* bs = h ? Blo : Bhi;
            {
                int r = tid >> 2, seg = tid & 3;
                uint32_t dst = smem_u32(sB + ((st * 2 + h) * 64 + r) * APAD + seg * 8);
                CP_ASYNC16(dst, bs + (size_t)(n0b + r) * 1024 + k0 + seg * 8);
            }
        }
    };

    load_stage(0, 0);  CP_COMMIT();
    load_stage(1, 32); CP_COMMIT();
    load_stage(2, 64); CP_COMMIT();

    const int NC = 1024 / 32;
    for (int c = 0; c < NC; c++) {
        CP_WAIT2();
        __syncthreads();
        const int st = c % 3;
        __nv_bfloat16* aH = sA + (st * 2 + 0) * 128 * APAD;
        __nv_bfloat16* aL = sA + (st * 2 + 1) * 128 * APAD;
        __nv_bfloat16* bH = sB + (st * 2 + 0) * 64 * APAD;
        __nv_bfloat16* bL = sB + (st * 2 + 1) * 64 * APAD;
#pragma unroll
        for (int kk = 0; kk < 32; kk += 16) {
            uint32_t aHi[2][4], aLo[2][4], bHi[4][2], bLo[4][2];
#pragma unroll
            for (int mt = 0; mt < 2; mt++) {
                uint32_t ah = smem_u32(aH + (mw + mt * 16 + arow) * APAD + kk + acol0);
                LDSM_X4(aHi[mt][0], aHi[mt][1], aHi[mt][2], aHi[mt][3], ah);
                uint32_t al = smem_u32(aL + (mw + mt * 16 + arow) * APAD + kk + acol0);
                LDSM_X4(aLo[mt][0], aLo[mt][1], aLo[mt][2], aLo[mt][3], al);
            }
#pragma unroll
            for (int nt = 0; nt < 4; nt++) {
                uint32_t bh = smem_u32(bH + (nw + nt * 8 + brow) * APAD + kk + bcol0);
                LDSM_X2(bHi[nt][0], bHi[nt][1], bh);
                uint32_t bl = smem_u32(bL + (nw + nt * 8 + brow) * APAD + kk + bcol0);
                LDSM_X2(bLo[nt][0], bLo[nt][1], bl);
            }
#pragma unroll
            for (int mt = 0; mt < 2; mt++)
#pragma unroll
                for (int nt = 0; nt < 4; nt++) {
                    mma16816(acc[mt][nt], aHi[mt], bHi[nt]);
                    mma16816(acc[mt][nt], aHi[mt], bLo[nt]);
                    mma16816(acc[mt][nt], aLo[mt], bHi[nt]);
                }
        }
        __syncthreads();
        if (c + 3 < NC) load_stage(st, (c + 3) * 32);
        CP_COMMIT();
    }

    const int proj = n0b >> 10;
    const float* bias = (mode == 0) ? bias0
                        : (proj == 0 ? bias0 : (proj == 1 ? bias1 : bias2));

#pragma unroll
    for (int mt = 0; mt < 2; mt++) {
        int r = m0 + mw + mt * 16 + (lane >> 2);
#pragma unroll
        for (int nt = 0; nt < 4; nt++) {
            int n = n0b + nw + nt * 8 + (lane & 3) * 2;
            int nn = n & 1023;
            float v0 = acc[mt][nt][0] + bias[nn], v1 = acc[mt][nt][1] + bias[nn + 1];
            float v2 = acc[mt][nt][2] + bias[nn], v3 = acc[mt][nt][3] + bias[nn + 1];
            if (mode == 0) {
                *(float2*)&C[(size_t)r * 1024 + n] = make_float2(v0, v1);
                *(float2*)&C[(size_t)(r + 8) * 1024 + n] = make_float2(v2, v3);
            } else {
                int h = nn >> 6, d = nn & 63;
                int b = r >> 11, s = r & (SEQ - 1);
                int b2 = (r + 8) >> 11, s2 = (r + 8) & (SEQ - 1);
                if (proj < 2) {
                    size_t base = (size_t)proj * NHSD;
                    size_t o1 = base + (((size_t)(b * NH + h)) * SEQ + s) * DKV + d;
                    size_t o2 = base + (((size_t)(b2 * NH + h)) * SEQ + s2) * DKV + d;
                    uint32_t hi, lo;
                    split2(v0, v1, hi, lo);
                    *(uint32_t*)&g_qkvhi[o1] = hi; *(uint32_t*)&g_qkvlo[o1] = lo;
                    split2(v2, v3, hi, lo);
                    *(uint32_t*)&g_qkvhi[o2] = hi; *(uint32_t*)&g_qkvlo[o2] = lo;
                } else {
                    size_t vb1 = ((size_t)(b * NH + h)) * DKV * SEQ;
                    size_t vb2 = ((size_t)(b2 * NH + h)) * DKV * SEQ;
                    __nv_bfloat16 hh, ll;
                    split1(v0, hh, ll);
                    g_vthi[vb1 + (size_t)d * SEQ + s] = hh; g_vtlo[vb1 + (size_t)d * SEQ + s] = ll;
                    split1(v1, hh, ll);
                    g_vthi[vb1 + (size_t)(d + 1) * SEQ + s] = hh; g_vtlo[vb1 + (size_t)(d + 1) * SEQ + s] = ll;
                    split1(v2, hh, ll);
                    g_vthi[vb2 + (size_t)d * SEQ + s2] = hh; g_vtlo[vb2 + (size_t)d * SEQ + s2] = ll;
                    split1(v3, hh, ll);
                    g_vthi[vb2 + (size_t)(d + 1) * SEQ + s2] = hh; g_vtlo[vb2 + (size_t)(d + 1) * SEQ + s2] = ll;
                }
            }
        }
    }
}

// ---------------- scores = Q K^T + bias + mask, with fused softmax stats ----------------
#define QKPAD 72
#define QK_TILE (2 * 128 * QKPAD)                 // bf16 elems per (hi+lo) tile
#define QK_STATS_FLOATS (256 + 128 + 256 + 128 + 128)
#define QK_SMEM ((QK_TILE * 3) * 2 + QK_STATS_FLOATS * 4)

__global__ __launch_bounds__(256) void qk_mma_kernel(float* __restrict__ wts) {
    extern __shared__ char qsm_raw[];
    __nv_bfloat16* sQ = (__nv_bfloat16*)qsm_raw;  // [half][128][QKPAD]
    __nv_bfloat16* sK = sQ + QK_TILE;             // [st][half][128][QKPAD]
    float* sBias = (float*)(sQ + QK_TILE * 3);    // [256]
    float* sMask = sBias + 256;                   // [128]
    float* sPart = sMask + 128;                   // [2][128]
    float* sMax  = sPart + 256;                   // [128]
    float* sSum  = sMax + 128;                    // [128]

    const int tid = threadIdx.x, wid = tid >> 5, lane = tid & 31;
    const int q0 = blockIdx.x * 128;
    const int bh = blockIdx.y;
    const int hh = bh & 15, bq = bh >> 4;
    const size_t base = (size_t)bh * SEQ * DKV;
    float* sp = wts + (size_t)bh * SEQ * SEQ;

    const __nv_bfloat16* qhi = g_qkvhi;
    const __nv_bfloat16* qlo = g_qkvlo;
    const __nv_bfloat16* khi = g_qkvhi + NHSD;
    const __nv_bfloat16* klo = g_qkvlo + NHSD;

    const int mw = (wid & 3) * 32;
    const int nw = (wid >> 2) * 64;
    const int colhalf = wid >> 2;
    const int arow = lane & 15;
    const int acol0 = (lane >> 4) << 3;
    const int brow = lane & 7;
    const int bcol0 = ((lane >> 3) & 1) << 3;

    // Q tile (persistent, synchronous)
#pragma unroll
    for (int it = 0; it < 4; it++) {
        int i = tid + it * 256;
        int r = i >> 3, seg = i & 7;
        size_t o = base + (size_t)(q0 + r) * DKV + seg * 8;
        *(uint4*)(sQ + r * QKPAD + seg * 8) = *(const uint4*)(qhi + o);
        *(uint4*)(sQ + (128 + r) * QKPAD + seg * 8) = *(const uint4*)(qlo + o);
    }

    auto load_k = [&](int st, int kt) {
#pragma unroll
        for (int h = 0; h < 2; h++) {
            const __nv_bfloat16* ks = h ? klo : khi;
#pragma unroll
            for (int it = 0; it < 4; it++) {
                int i = tid + it * 256;
                int r = i >> 3, seg = i & 7;
                uint32_t dst = smem_u32(sK + ((st * 2 + h) * 128 + r) * QKPAD + seg * 8);
                CP_ASYNC16(dst, ks + base + (size_t)(kt * 128 + r) * DKV + seg * 8);
            }
        }
    };

    load_k(0, 0); CP_COMMIT();
    load_k(1, 1); CP_COMMIT();

    for (int kt = 0; kt < 16; kt++) {
        if (kt == 15) CP_WAIT0(); else CP_WAIT1();
        __syncthreads();
        const int st = kt & 1;
        __nv_bfloat16* kH = sK + (st * 2 + 0) * 128 * QKPAD;
        __nv_bfloat16* kL = sK + (st * 2 + 1) * 128 * QKPAD;

        // stage bias (255 used of 256) + key mask for this tile
        // FIX(R13): block has 256 threads — all load bias, first 128 also load mask
        {
            int base_delta = kt * 128 - q0 + 1920;      // j in [0,255)
            sBias[tid] = g_bias[(hh << 12) + base_delta + tid];
            if (tid < 128) sMask[tid] = g_maskf[bq * SEQ + kt * 128 + tid];
        }

        float acc[2][8][4];
#pragma unroll
        for (int mt = 0; mt < 2; mt++)
#pragma unroll
            for (int nt = 0; nt < 8; nt++)
#pragma unroll
                for (int i = 0; i < 4; i++) acc[mt][nt][i] = 0.f;

#pragma unroll
        for (int kk = 0; kk < 64; kk += 16) {
            uint32_t aHi[2][4], aLo[2][4];
#pragma unroll
            for (int mt = 0; mt < 2; mt++) {
                uint32_t ah = smem_u32(sQ + (mw + mt * 16 + arow) * QKPAD + kk + acol0);
                LDSM_X4(aHi[mt][0], aHi[mt][1], aHi[mt][2], aHi[mt][3], ah);
                uint32_t al = smem_u32(sQ + (128 + mw + mt * 16 + arow) * QKPAD + kk + acol0);
                LDSM_X4(aLo[mt][0], aLo[mt][1], aLo[mt][2], aLo[mt][3], al);
            }
#pragma unroll
            for (int g = 0; g < 2; g++) {
                uint32_t bHi[4][2], bLo[4][2];
#pragma unroll
                for (int j = 0; j < 4; j++) {
                    int nt = g * 4 + j;
                    uint32_t bh2 = smem_u32(kH + (nw + nt * 8 + brow) * QKPAD + kk + bcol0);
                    LDSM_X2(bHi[j][0], bHi[j][1], bh2);
                    uint32_t bl2 = smem_u32(kL + (nw + nt * 8 + brow) * QKPAD + kk + bcol0);
                    LDSM_X2(bLo[j][0], bLo[j][1], bl2);
                }
#pragma unroll
                for (int mt = 0; mt < 2; mt++)
#pragma unroll
                    for (int j = 0; j < 4; j++) {
                        int nt = g * 4 + j;
                        mma16816(acc[mt][nt], aHi[mt], bHi[j]);
                        mma16816(acc[mt][nt], aHi[mt], bLo[j]);
                        mma16816(acc[mt][nt], aLo[mt], bHi[j]);
                    }
            }
        }

        __syncthreads();   // sBias/sMask visible; previous kt's sPart readers done

        // apply bias+mask, write raw scores, row tile-max
        const int r1 = mw + (lane >> 2);           // mt=0 rows r1, r1+8; mt=1: +16
        float tmax[2][2] = {{-INFINITY, -INFINITY}, {-INFINITY, -INFINITY}};
#pragma unroll
        for (int mt = 0; mt < 2; mt++) {
            int rA = r1 + mt * 16, rB = rA + 8;
            float* row0 = sp + (size_t)(q0 + rA) * SEQ + kt * 128;
            float* row1 = row0 + 8 * SEQ;
#pragma unroll
            for (int nt = 0; nt < 8; nt++) {
                int c = nw + nt * 8 + (lane & 3) * 2;
                float mk0 = sMask[c], mk1 = sMask[c + 1];
                float b0 = sBias[c - rA + 127], b1 = sBias[c + 1 - rA + 127];
                float b2 = sBias[c - rB + 127], b3 = sBias[c + 1 - rB + 127];
                acc[mt][nt][0] += b0 + mk0;  acc[mt][nt][1] += b1 + mk1;
                acc[mt][nt][2] += b2 + mk0;  acc[mt][nt][3] += b3 + mk1;
                *(float2*)&row0[c] = make_float2(acc[mt][nt][0], acc[mt][nt][1]);
                *(float2*)&row1[c] = make_float2(acc[mt][nt][2], acc[mt][nt][3]);
                tmax[mt][0] = fmaxf(tmax[mt][0], fmaxf(acc[mt][nt][0], acc[mt][nt][1]));
                tmax[mt][1] = fmaxf(tmax[mt][1], fmaxf(acc[mt][nt][2], acc[mt][nt][3]));
            }
#pragma unroll
            for (int hv = 0; hv < 2; hv++) {
                tmax[mt][hv] = fmaxf(tmax[mt][hv], __shfl_xor_sync(0xffffffffu, tmax[mt][hv], 1));
                tmax[mt][hv] = fmaxf(tmax[mt][hv], __shfl_xor_sync(0xffffffffu, tmax[mt][hv], 2));
            }
            if ((lane & 3) == 0) {
                sPart[colhalf * 128 + rA] = tmax[mt][0];
                sPart[colhalf * 128 + rB] = tmax[mt][1];
            }
        }
        __syncthreads();

        // running-max update + sum rescale (one thread per row)
        if (tid < 128) {
            float tm = fmaxf(sPart[tid], sPart[128 + tid]);
            if (kt == 0) { sMax[tid] = tm; sSum[tid] = 0.f; }
            else {
                float mo = sMax[tid];
                float mn = fmaxf(mo, tm);
                sSum[tid] *= __expf(mo - mn);
                sMax[tid] = mn;
            }
        }
        __syncthreads();

        // partial exp-sums against updated max
#pragma unroll
        for (int mt = 0; mt < 2; mt++) {
            int rA = r1 + mt * 16, rB = rA + 8;
            float mA = sMax[rA], mB = sMax[rB];
            float pA = 0.f, pB = 0.f;
#pragma unroll
            for (int nt = 0; nt < 8; nt++) {
                pA += __expf(acc[mt][nt][0] - mA) + __expf(acc[mt][nt][1] - mA);
                pB += __expf(acc[mt][nt][2] - mB) + __expf(acc[mt][nt][3] - mB);
            }
            pA += __shfl_xor_sync(0xffffffffu, pA, 1);
            pA += __shfl_xor_sync(0xffffffffu, pA, 2);
            pB += __shfl_xor_sync(0xffffffffu, pB, 1);
            pB += __shfl_xor_sync(0xffffffffu, pB, 2);
            if ((lane & 3) == 0) {
                sPart[colhalf * 128 + rA] = pA;
                sPart[colhalf * 128 + rB] = pB;
            }
        }
        __syncthreads();
        if (tid < 128) sSum[tid] += sPart[tid] + sPart[128 + tid];
        __syncthreads();

        if (kt + 2 < 16) { load_k(st, kt + 2); CP_COMMIT(); }
    }

    if (tid < 128)
        g_stats[(size_t)bh * SEQ + q0 + tid] = make_float2(sMax[tid], 1.0f / sSum[tid]);
}

// ---------------- ctx = softmax(scores) @ V, fused normalize + weights writeback ----------------
#define WV_W_ELE (2 * 128 * APAD)
#define WV_V_ELE (2 * 64 * APAD)
#define WV_SMEM (WV_W_ELE * 2 + 2 * WV_V_ELE * 2 + 2 * 128 * 32 * 4)

__global__ __launch_bounds__(256) void wv_mma_kernel(float* __restrict__ wts) {
    extern __shared__ char wsm_raw[];
    __nv_bfloat16* sW = (__nv_bfloat16*)wsm_raw;             // [half][128][APAD]
    __nv_bfloat16* sV = sW + WV_W_ELE;                        // [st][half][64][APAD]
    float* sWraw = (float*)(sV + 2 * WV_V_ELE);               // [st][128][32]
    __shared__ float sM[128], sInv[128];

    const int tid = threadIdx.x, wid = tid >> 5, lane = tid & 31;
    const int m0 = blockIdx.x * 128;
    const int bh = blockIdx.y;
    const int b = bh >> 4, h = bh & 15;
    float* wp = wts + (size_t)bh * SEQ * SEQ;
    const __nv_bfloat16* vh = g_vthi + (size_t)bh * DKV * SEQ;
    const __nv_bfloat16* vl = g_vtlo + (size_t)bh * DKV * SEQ;

    if (tid < 128) {
        float2 st = g_stats[(size_t)bh * SEQ + m0 + tid];
        sM[tid] = st.x;
        sInv[tid] = st.y;
    }

    const int mw = (wid & 3) * 32;
    const int nw = (wid >> 2) * 32;
    const int arow = lane & 15;
    const int acol0 = (lane >> 4) << 3;
    const int brow = lane & 7;
    const int bcol0 = ((lane >> 3) & 1) << 3;

    float acc[2][4][4];
#pragma unroll
    for (int mt = 0; mt < 2; mt++)
#pragma unroll
        for (int nt = 0; nt < 4; nt++)
#pragma unroll
            for (int i = 0; i < 4; i++) acc[mt][nt][i] = 0.f;

    auto load_stage = [&](int st, int k0) {
#pragma unroll
        for (int hh = 0; hh < 2; hh++) {
            const __nv_bfloat16* vs = hh ? vl : vh;
            int r = tid >> 2, seg = tid & 3;
            uint32_t dst = smem_u32(sV + ((st * 2 + hh) * 64 + r) * APAD + seg * 8);
            CP_ASYNC16(dst, vs + (size_t)r * SEQ + k0 + seg * 8);
        }
#pragma unroll
        for (int it = 0; it < 4; it++) {
            int i = tid + it * 256;
            int r = i >> 3, seg = i & 7;
            uint32_t dst = smem_u32(sWraw + (st * 128 + r) * 32 + seg * 4);
            CP_ASYNC16(dst, wp + (size_t)(m0 + r) * SEQ + k0 + seg * 4);
        }
    };

    load_stage(0, 0);  CP_COMMIT();
    load_stage(1, 32); CP_COMMIT();

    const int NC = SEQ / 32;
    for (int c = 0; c < NC; c++) {
        if (c == NC - 1) CP_WAIT0(); else CP_WAIT1();
        __syncthreads();
        const int st = c & 1;
        // normalize raw scores -> weights; write back (output) + hi/lo for MMA
#pragma unroll
        for (int it = 0; it < 4; it++) {
            int i = tid + it * 256;
            int r = i >> 3, seg = i & 7;
            float4 v = *(float4*)(sWraw + (st * 128 + r) * 32 + seg * 4);
            float m = sM[r], iv = sInv[r];
            v.x = __expf(v.x - m) * iv;
            v.y = __expf(v.y - m) * iv;
            v.z = __expf(v.z - m) * iv;
            v.w = __expf(v.w - m) * iv;
            *(float4*)(wp + (size_t)(m0 + r) * SEQ + c * 32 + seg * 4) = v;
            uint2 H, L;
            split2(v.x, v.y, H.x, L.x);
            split2(v.z, v.w, H.y, L.y);
            *(uint2*)(sW + r * APAD + seg * 4) = H;
            *(uint2*)(sW + (128 + r) * APAD + seg * 4) = L;
        }
        __syncthreads();

        __nv_bfloat16* vH = sV + (st * 2 + 0) * 64 * APAD;
        __nv_bfloat16* vL = sV + (st * 2 + 1) * 64 * APAD;
#pragma unroll
        for (int kk = 0; kk < 32; kk += 16) {
            uint32_t aHi[2][4], aLo[2][4], bHi[4][2], bLo[4][2];
#pragma unroll
            for (int mt = 0; mt < 2; mt++) {
                uint32_t ah = smem_u32(sW + (mw + mt * 16 + arow) * APAD + kk + acol0);
                LDSM_X4(aHi[mt][0], aHi[mt][1], aHi[mt][2], aHi[mt][3], ah);
                uint32_t al = smem_u32(sW + (128 + mw + mt * 16 + arow) * APAD + kk + acol0);
                LDSM_X4(aLo[mt][0], aLo[mt][1], aLo[mt][2], aLo[mt][3], al);
            }
#pragma unroll
            for (int nt = 0; nt < 4; nt++) {
                uint32_t bh2 = smem_u32(vH + (nw + nt * 8 + brow) * APAD + kk + bcol0);
                LDSM_X2(bHi[nt][0], bHi[nt][1], bh2);
                uint32_t bl2 = smem_u32(vL + (nw + nt * 8 + brow) * APAD + kk + bcol0);
                LDSM_X2(bLo[nt][0], bLo[nt][1], bl2);
            }
#pragma unroll
            for (int mt = 0; mt < 2; mt++)
#pragma unroll
                for (int nt = 0; nt < 4; nt++) {
                    mma16816(acc[mt][nt], aHi[mt], bHi[nt]);
                    mma16816(acc[mt][nt], aHi[mt], bLo[nt]);
                    mma16816(acc[mt][nt], aLo[mt], bHi[nt]);
                }
        }
        __syncthreads();
        if (c + 2 < NC) { load_stage(st, (c + 2) * 32); CP_COMMIT(); }
    }

#pragma unroll
    for (int mt = 0; mt < 2; mt++) {
        int s = m0 + mw + mt * 16 + (lane >> 2);
#pragma unroll
        for (int nt = 0; nt < 4; nt++) {
            int d = nw + nt * 8 + (lane & 3) * 2;
            size_t o1 = ((size_t)(b * SEQ + s)) * INNER + h * DKV + d;
            size_t o2 = ((size_t)(b * SEQ + s + 8)) * INNER + h * DKV + d;
            uint32_t hi, lo;
            split2(acc[mt][nt][0], acc[mt][nt][1], hi, lo);
            *(uint32_t*)&g_chi[o1] = hi; *(uint32_t*)&g_clo[o1] = lo;
            split2(acc[mt][nt][2], acc[mt][nt][3], hi, lo);
            *(uint32_t*)&g_chi[o2] = hi; *(uint32_t*)&g_clo[o2] = lo;
        }
    }
}

// ---------------- launch ----------------
extern "C" void kernel_launch(void* const* d_in, const int* in_sizes, int n_in,
                              void* d_out, int out_size) {
    const float* x  = (const float*)d_in[0];
    const float* Wq = (const float*)d_in[1];
    const float* bq = (const float*)d_in[2];
    const float* Wk = (const float*)d_in[3];
    const float* bk = (const float*)d_in[4];
    const float* Wv = (const float*)d_in[5];
    const float* bv = (const float*)d_in[6];
    const float* Wo = (const float*)d_in[7];
    const float* bo = (const float*)d_in[8];
    const float* rel_table = (const float*)d_in[9];
    const unsigned char* mask = (const unsigned char*)d_in[10];

    float* out = (float*)d_out;
    float* wts = out + (size_t)BSZ * SEQ * DMODEL;
    float* pb  = wts + (size_t)BSZ * NH * SEQ * SEQ;

    __nv_bfloat16 *pxhi, *pxlo, *pwhi, *pwlo, *pchi, *pclo;
    cudaGetSymbolAddress((void**)&pxhi, g_xhi);
    cudaGetSymbolAddress((void**)&pxlo, g_xlo);
    cudaGetSymbolAddress((void**)&pwhi, g_whi);
    cudaGetSymbolAddress((void**)&pwlo, g_wlo);
    cudaGetSymbolAddress((void**)&pchi, g_chi);
    cudaGetSymbolAddress((void**)&pclo, g_clo);

    cudaFuncSetAttribute(mma_gemm_kernel,
                         cudaFuncAttributeMaxDynamicSharedMemorySize, GEMM_SMEM);
    cudaFuncSetAttribute(qk_mma_kernel,
                         cudaFuncAttributeMaxDynamicSharedMemorySize, QK_SMEM);
    cudaFuncSetAttribute(wv_mma_kernel,
                         cudaFuncAttributeMaxDynamicSharedMemorySize, WV_SMEM);

    const size_t WSTRIDE = (size_t)DMODEL * INNER;

    // launch 1: all preprocessing
    prep_kernel<<<NCVT + NTRANS + 256 + 1, 256>>>(x, Wq, Wk, Wv, Wo, rel_table, mask);

    // launch 2: fused QKV projection (N = 3072)
    mma_gemm_kernel<<<dim3(3 * INNER / 64, MTOT / 128), 256, GEMM_SMEM>>>(
        pxhi, pxlo, pwhi, pwlo, bq, bk, bv, nullptr, 1);

    // launch 3: pos_bias output
    posbias_kernel<<<(NH * (size_t)SEQ * SEQ) / 256, 256>>>(pb);

    // launch 4: scores + fused softmax stats  (ncu capture target)
    qk_mma_kernel<<<dim3(SEQ / 128, BSZ * NH), 256, QK_SMEM>>>(wts);

    // launch 5: normalize + weights writeback + ctx
    wv_mma_kernel<<<dim3(SEQ / 128, BSZ * NH), 256, WV_SMEM>>>(wts);

    // launch 6: output projection
    mma_gemm_kernel<<<dim3(INNER / 64, MTOT / 128), 256, GEMM_SMEM>>>(
        pchi, pclo, pwhi + 3 * WSTRIDE, pwlo + 3 * WSTRIDE, bo, bo, bo, out, 0);
}

// round 17
// speedup vs baseline: 1.0061x; 1.0061x over previous
#include <cuda_runtime.h>
#include <cuda_bf16.h>
#include <math.h>
#include <stdint.h>

#define BSZ 2
#define SEQ 2048
#define NH 16
#define DKV 64
#define DMODEL 1024
#define INNER 1024
#define MTOT (BSZ * SEQ)   // 4096
#define NHSD (BSZ * NH * SEQ * DKV)   // 4194304

// ---------------- scratch (static device memory; no allocations) ----------------
__device__ float g_bias[NH * 4096];
__device__ float g_maskf[BSZ * SEQ];
__device__ float2 g_stats[BSZ * NH * SEQ];             // per-row (max, 1/sum)
__device__ __nv_bfloat16 g_xhi[MTOT * DMODEL];
__device__ __nv_bfloat16 g_xlo[MTOT * DMODEL];
__device__ __nv_bfloat16 g_whi[4u * DMODEL * INNER];   // [n][k]; 0=Wq 1=Wk 2=Wv 3=Wo (contiguous)
__device__ __nv_bfloat16 g_wlo[4u * DMODEL * INNER];
__device__ __nv_bfloat16 g_qkvhi[2 * NHSD];            // Q then K  (b,h,s,d)
__device__ __nv_bfloat16 g_qkvlo[2 * NHSD];
__device__ __nv_bfloat16 g_vthi[NHSD];                 // V transposed (b,h,d,s)
__device__ __nv_bfloat16 g_vtlo[NHSD];
__device__ __nv_bfloat16 g_chi[MTOT * INNER];          // (b,s,inner)
__device__ __nv_bfloat16 g_clo[MTOT * INNER];

// ---------------- PTX helpers ----------------
__device__ __forceinline__ uint32_t smem_u32(const void* p) {
    uint32_t a;
    asm("{ .reg .u64 t; cvta.to.shared.u64 t, %1; cvt.u32.u64 %0, t; }" : "=r"(a) : "l"(p));
    return a;
}
#define LDSM_X4(r0, r1, r2, r3, addr) \
    asm volatile("ldmatrix.sync.aligned.m8n8.x4.shared.b16 {%0,%1,%2,%3}, [%4];" \
                 : "=r"(r0), "=r"(r1), "=r"(r2), "=r"(r3) : "r"(addr))
#define LDSM_X2(r0, r1, addr) \
    asm volatile("ldmatrix.sync.aligned.m8n8.x2.shared.b16 {%0,%1}, [%2];" \
                 : "=r"(r0), "=r"(r1) : "r"(addr))
#define CP_ASYNC16(dst, src) \
    asm volatile("cp.async.cg.shared.global [%0], [%1], 16;" :: "r"(dst), "l"(src))
#define CP_COMMIT() asm volatile("cp.async.commit_group;" ::: "memory")
#define CP_WAIT0()  asm volatile("cp.async.wait_group 0;" ::: "memory")
#define CP_WAIT1()  asm volatile("cp.async.wait_group 1;" ::: "memory")
#define CP_WAIT2()  asm volatile("cp.async.wait_group 2;" ::: "memory")

__device__ __forceinline__ void mma16816(float* c, const uint32_t* a, const uint32_t* b) {
    asm volatile("mma.sync.aligned.m16n8k16.row.col.f32.bf16.bf16.f32 "
                 "{%0,%1,%2,%3}, {%4,%5,%6,%7}, {%8,%9}, {%0,%1,%2,%3};"
                 : "+f"(c[0]), "+f"(c[1]), "+f"(c[2]), "+f"(c[3])
                 : "r"(a[0]), "r"(a[1]), "r"(a[2]), "r"(a[3]), "r"(b[0]), "r"(b[1]));
}

__device__ __forceinline__ void split2(float v0, float v1, uint32_t& hi, uint32_t& lo) {
    __nv_bfloat16 h0 = __float2bfloat16(v0), h1 = __float2bfloat16(v1);
    __nv_bfloat16 l0 = __float2bfloat16(v0 - __bfloat162float(h0));
    __nv_bfloat16 l1 = __float2bfloat16(v1 - __bfloat162float(h1));
    hi = (uint32_t)__bfloat16_as_ushort(h0) | ((uint32_t)__bfloat16_as_ushort(h1) << 16);
    lo = (uint32_t)__bfloat16_as_ushort(l0) | ((uint32_t)__bfloat16_as_ushort(l1) << 16);
}
__device__ __forceinline__ void split1(float v, __nv_bfloat16& h, __nv_bfloat16& l) {
    h = __float2bfloat16(v);
    l = __float2bfloat16(v - __bfloat162float(h));
}

// ---------------- T5 relative-position bucket ----------------
__device__ __forceinline__ int rel_bucket(int delta) {
    int ret = (delta > 0) ? 32 : 0;
    int n = (delta < 0) ? -delta : delta;
    if (n < 16) return ret + n;
    float t = logf((float)n / 16.0f);
    t = t / 1.1394342831883648f;
    t = t * 16.0f;
    int large = 16 + (int)t;
    if (large > 31) large = 31;
    return ret + large;
}

// ---------------- combined prep: cvt | weight transpose | biasfill | maskprep ----------------
#define NCVT 4096           // (MTOT*DMODEL)/1024
#define NTRANS 4096         // 32*32*4
__global__ void prep_kernel(const float* __restrict__ x,
                            const float* __restrict__ w0, const float* __restrict__ w1,
                            const float* __restrict__ w2, const float* __restrict__ w3,
                            const float* __restrict__ rel_table,
                            const unsigned char* __restrict__ mraw) {
    const int blk = blockIdx.x;
    const int tid = threadIdx.x;
    if (blk < NCVT) {
        size_t i = ((size_t)blk * 256 + tid) * 4;
        float4 v = *(const float4*)(x + i);
        uint2 H, L;
        split2(v.x, v.y, H.x, L.x);
        split2(v.z, v.w, H.y, L.y);
        *(uint2*)(g_xhi + i) = H;
        *(uint2*)(g_xlo + i) = L;
    } else if (blk < NCVT + NTRANS) {
        __shared__ float t[32][33];
        int b2 = blk - NCVT;
        int z = b2 >> 10, rem = b2 & 1023;
        const float* src = (z == 0) ? w0 : (z == 1) ? w1 : (z == 2) ? w2 : w3;
        __nv_bfloat16* dhi = g_whi + (size_t)z * DMODEL * INNER;
        __nv_bfloat16* dlo = g_wlo + (size_t)z * DMODEL * INNER;
        int tx = tid & 31, ty = tid >> 5;
        int n0 = (rem & 31) * 32, k0 = (rem >> 5) * 32;
#pragma unroll
        for (int j = 0; j < 32; j += 8)
            t[ty + j][tx] = src[(size_t)(k0 + ty + j) * INNER + n0 + tx];
        __syncthreads();
#pragma unroll
        for (int j = 0; j < 32; j += 8) {
            float v = t[tx][ty + j];
            int n = n0 + ty + j, k = k0 + tx;
            __nv_bfloat16 h = __float2bfloat16(v);
            dhi[(size_t)n * DMODEL + k] = h;
            dlo[(size_t)n * DMODEL + k] = __float2bfloat16(v - __bfloat162float(h));
        }
    } else if (blk < NCVT + NTRANS + 256) {
        int idx = (blk - NCVT - NTRANS) * 256 + tid;     // NH*4096 = 65536
        int h = idx >> 12;
        int dd = idx & 4095;
        int delta = dd - (SEQ - 1);
        if (dd >= 2 * SEQ - 1) delta = 0;
        g_bias[idx] = rel_table[rel_bucket(delta) * NH + h];
    } else {
        // mask prep (bool stored as int32 or u8 — detect)
        __shared__ int s_nonzero;
        if (tid == 0) s_nonzero = 0;
        __syncthreads();
        int cnt = 0;
        for (int i = tid; i < BSZ * SEQ; i += 256)
            if ((i & 3) && mraw[i]) cnt++;
        if (cnt) atomicAdd(&s_nonzero, cnt);
        __syncthreads();
        const bool is_u8 = (s_nonzero > 0);
        const int* mi = (const int*)mraw;
        for (int i = tid; i < BSZ * SEQ; i += 256) {
            int flag = is_u8 ? (int)mraw[i] : mi[i];
            g_maskf[i] = flag ? -INFINITY : 0.0f;
        }
    }
}

// ---------------- pos_bias output (1,h,q,k) ----------------
__global__ void posbias_kernel(float* __restrict__ pb) {
    size_t idx = (size_t)blockIdx.x * 256 + threadIdx.x;   // NH*SEQ*SEQ
    int k = (int)(idx & (SEQ - 1));
    int q = (int)((idx >> 11) & (SEQ - 1));
    int h = (int)(idx >> 22);
    pb[idx] = g_bias[(h << 12) + (k - q + SEQ - 1)];
}

// ---------------- 3-stage pipelined mma.sync GEMM ----------------
#define APAD 40
#define GA_ELE (2 * 128 * APAD)
#define GB_ELE (2 * 64 * APAD)
#define GEMM_SMEM ((3 * (GA_ELE + GB_ELE)) * 2)

__global__ __launch_bounds__(256) void mma_gemm_kernel(
    const __nv_bfloat16* __restrict__ Ahi, const __nv_bfloat16* __restrict__ Alo,
    const __nv_bfloat16* __restrict__ Bhi, const __nv_bfloat16* __restrict__ Blo,
    const float* __restrict__ bias0, const float* __restrict__ bias1,
    const float* __restrict__ bias2, float* __restrict__ C, int mode)
{
    extern __shared__ char gsm_raw[];
    __nv_bfloat16* sA = (__nv_bfloat16*)gsm_raw;
    __nv_bfloat16* sB = sA + 3 * GA_ELE;

    const int tid = threadIdx.x;
    const int wid = tid >> 5, lane = tid & 31;
    const int m0 = blockIdx.y * 128;
    const int n0b = blockIdx.x * 64;
    const int mw = (wid & 3) * 32;
    const int nw = (wid >> 2) * 32;

    float acc[2][4][4];
#pragma unroll
    for (int mt = 0; mt < 2; mt++)
#pragma unroll
        for (int nt = 0; nt < 4; nt++)
#pragma unroll
            for (int i = 0; i < 4; i++) acc[mt][nt][i] = 0.f;

    const int arow = lane & 15;
    const int acol0 = (lane >> 4) << 3;
    const int brow = lane & 7;
    const int bcol0 = ((lane >> 3) & 1) << 3;

    auto load_stage = [&](int st, int k0) {
#pragma unroll
        for (int h = 0; h < 2; h++) {
            const __nv_bfloat16* as = h ? Alo : Ahi;
#pragma unroll
            for (int it = 0; it < 2; it++) {
                int idx = tid + it * 256;
                int r = idx >> 2, seg = idx & 3;
                uint32_t dst = smem_u32(sA + ((st * 2 + h) * 128 + r) * APAD + seg * 8);
                CP_ASYNC16(dst, as + (size_t)(m0 + r) * 1024 + k0 + seg * 8);
            }
            const __nv_bfloat16* bs = h ? Blo : Bhi;
            {
                int r = tid >> 2, seg = tid & 3;
                uint32_t dst = smem_u32(sB + ((st * 2 + h) * 64 + r) * APAD + seg * 8);
                CP_ASYNC16(dst, bs + (size_t)(n0b + r) * 1024 + k0 + seg * 8);
            }
        }
    };

    load_stage(0, 0);  CP_COMMIT();
    load_stage(1, 32); CP_COMMIT();
    load_stage(2, 64); CP_COMMIT();

    const int NC = 1024 / 32;
    for (int c = 0; c < NC; c++) {
        CP_WAIT2();
        __syncthreads();
        const int st = c % 3;
        __nv_bfloat16* aH = sA + (st * 2 + 0) * 128 * APAD;
        __nv_bfloat16* aL = sA + (st * 2 + 1) * 128 * APAD;
        __nv_bfloat16* bH = sB + (st * 2 + 0) * 64 * APAD;
        __nv_bfloat16* bL = sB + (st * 2 + 1) * 64 * APAD;
#pragma unroll
        for (int kk = 0; kk < 32; kk += 16) {
            uint32_t aHi[2][4], aLo[2][4], bHi[4][2], bLo[4][2];
#pragma unroll
            for (int mt = 0; mt < 2; mt++) {
                uint32_t ah = smem_u32(aH + (mw + mt * 16 + arow) * APAD + kk + acol0);
                LDSM_X4(aHi[mt][0], aHi[mt][1], aHi[mt][2], aHi[mt][3], ah);
                uint32_t al = smem_u32(aL + (mw + mt * 16 + arow) * APAD + kk + acol0);
                LDSM_X4(aLo[mt][0], aLo[mt][1], aLo[mt][2], aLo[mt][3], al);
            }
#pragma unroll
            for (int nt = 0; nt < 4; nt++) {
                uint32_t bh = smem_u32(bH + (nw + nt * 8 + brow) * APAD + kk + bcol0);
                LDSM_X2(bHi[nt][0], bHi[nt][1], bh);
                uint32_t bl = smem_u32(bL + (nw + nt * 8 + brow) * APAD + kk + bcol0);
                LDSM_X2(bLo[nt][0], bLo[nt][1], bl);
            }
#pragma unroll
            for (int mt = 0; mt < 2; mt++)
#pragma unroll
                for (int nt = 0; nt < 4; nt++) {
                    mma16816(acc[mt][nt], aHi[mt], bHi[nt]);
                    mma16816(acc[mt][nt], aHi[mt], bLo[nt]);
                    mma16816(acc[mt][nt], aLo[mt], bHi[nt]);
                }
        }
        __syncthreads();
        if (c + 3 < NC) load_stage(st, (c + 3) * 32);
        CP_COMMIT();
    }

    const int proj = n0b >> 10;
    const float* bias = (mode == 0) ? bias0
                        : (proj == 0 ? bias0 : (proj == 1 ? bias1 : bias2));

#pragma unroll
    for (int mt = 0; mt < 2; mt++) {
        int r = m0 + mw + mt * 16 + (lane >> 2);
#pragma unroll
        for (int nt = 0; nt < 4; nt++) {
            int n = n0b + nw + nt * 8 + (lane & 3) * 2;
            int nn = n & 1023;
            float v0 = acc[mt][nt][0] + bias[nn], v1 = acc[mt][nt][1] + bias[nn + 1];
            float v2 = acc[mt][nt][2] + bias[nn], v3 = acc[mt][nt][3] + bias[nn + 1];
            if (mode == 0) {
                *(float2*)&C[(size_t)r * 1024 + n] = make_float2(v0, v1);
                *(float2*)&C[(size_t)(r + 8) * 1024 + n] = make_float2(v2, v3);
            } else {
                int h = nn >> 6, d = nn & 63;
                int b = r >> 11, s = r & (SEQ - 1);
                int b2 = (r + 8) >> 11, s2 = (r + 8) & (SEQ - 1);
                if (proj < 2) {
                    size_t base = (size_t)proj * NHSD;
                    size_t o1 = base + (((size_t)(b * NH + h)) * SEQ + s) * DKV + d;
                    size_t o2 = base + (((size_t)(b2 * NH + h)) * SEQ + s2) * DKV + d;
                    uint32_t hi, lo;
                    split2(v0, v1, hi, lo);
                    *(uint32_t*)&g_qkvhi[o1] = hi; *(uint32_t*)&g_qkvlo[o1] = lo;
                    split2(v2, v3, hi, lo);
                    *(uint32_t*)&g_qkvhi[o2] = hi; *(uint32_t*)&g_qkvlo[o2] = lo;
                } else {
                    size_t vb1 = ((size_t)(b * NH + h)) * DKV * SEQ;
                    size_t vb2 = ((size_t)(b2 * NH + h)) * DKV * SEQ;
                    __nv_bfloat16 hh, ll;
                    split1(v0, hh, ll);
                    g_vthi[vb1 + (size_t)d * SEQ + s] = hh; g_vtlo[vb1 + (size_t)d * SEQ + s] = ll;
                    split1(v1, hh, ll);
                    g_vthi[vb1 + (size_t)(d + 1) * SEQ + s] = hh; g_vtlo[vb1 + (size_t)(d + 1) * SEQ + s] = ll;
                    split1(v2, hh, ll);
                    g_vthi[vb2 + (size_t)d * SEQ + s2] = hh; g_vtlo[vb2 + (size_t)d * SEQ + s2] = ll;
                    split1(v3, hh, ll);
                    g_vthi[vb2 + (size_t)(d + 1) * SEQ + s2] = hh; g_vtlo[vb2 + (size_t)(d + 1) * SEQ + s2] = ll;
                }
            }
        }
    }
}

// ---------------- scores = Q K^T + bias + mask, fused softmax stats ----------------
// Q fragments held in registers; smem = 2 K stages + stats only (77 KB -> 2 CTAs/SM)
#define QKPAD 72
#define QK_STAGE_ELE (2 * 128 * QKPAD)            // one K stage (hi+lo) bf16 elems
#define QK_STATS_FLOATS (256 + 128 + 256 + 128 + 128)
#define QK_SMEM (2 * QK_STAGE_ELE * 2 + QK_STATS_FLOATS * 4)

__global__ __launch_bounds__(256) void qk_mma_kernel(float* __restrict__ wts) {
    extern __shared__ char qsm_raw[];
    __nv_bfloat16* sK = (__nv_bfloat16*)qsm_raw;  // [st][half][128][QKPAD]
    float* sBias = (float*)(sK + 2 * QK_STAGE_ELE);  // [256]
    float* sMask = sBias + 256;                   // [128]
    float* sPart = sMask + 128;                   // [2][128]
    float* sMax  = sPart + 256;                   // [128]
    float* sSum  = sMax + 128;                    // [128]

    const int tid = threadIdx.x, wid = tid >> 5, lane = tid & 31;
    const int q0 = blockIdx.x * 128;
    const int bh = blockIdx.y;
    const int hh = bh & 15, bq = bh >> 4;
    const size_t base = (size_t)bh * SEQ * DKV;
    float* sp = wts + (size_t)bh * SEQ * SEQ;

    const __nv_bfloat16* qhi = g_qkvhi;
    const __nv_bfloat16* qlo = g_qkvlo;
    const __nv_bfloat16* khi = g_qkvhi + NHSD;
    const __nv_bfloat16* klo = g_qkvlo + NHSD;

    const int mw = (wid & 3) * 32;
    const int nw = (wid >> 2) * 64;
    const int colhalf = wid >> 2;
    const int arow = lane & 15;
    const int acol0 = (lane >> 4) << 3;
    const int brow = lane & 7;
    const int bcol0 = ((lane >> 3) & 1) << 3;

    // stage Q tile through K stage-0 buffer, then pull fragments to registers
#pragma unroll
    for (int it = 0; it < 4; it++) {
        int i = tid + it * 256;
        int r = i >> 3, seg = i & 7;
        size_t o = base + (size_t)(q0 + r) * DKV + seg * 8;
        *(uint4*)(sK + r * QKPAD + seg * 8) = *(const uint4*)(qhi + o);
        *(uint4*)(sK + (128 + r) * QKPAD + seg * 8) = *(const uint4*)(qlo + o);
    }
    __syncthreads();

    uint32_t qH[4][2][4], qL[4][2][4];
#pragma unroll
    for (int ks = 0; ks < 4; ks++) {
        int kk = ks * 16;
#pragma unroll
        for (int mt = 0; mt < 2; mt++) {
            uint32_t ah = smem_u32(sK + (mw + mt * 16 + arow) * QKPAD + kk + acol0);
            LDSM_X4(qH[ks][mt][0], qH[ks][mt][1], qH[ks][mt][2], qH[ks][mt][3], ah);
            uint32_t al = smem_u32(sK + (128 + mw + mt * 16 + arow) * QKPAD + kk + acol0);
            LDSM_X4(qL[ks][mt][0], qL[ks][mt][1], qL[ks][mt][2], qL[ks][mt][3], al);
        }
    }
    __syncthreads();

    auto load_k = [&](int st, int kt) {
#pragma unroll
        for (int h = 0; h < 2; h++) {
            const __nv_bfloat16* ks = h ? klo : khi;
#pragma unroll
            for (int it = 0; it < 4; it++) {
                int i = tid + it * 256;
                int r = i >> 3, seg = i & 7;
                uint32_t dst = smem_u32(sK + ((st * 2 + h) * 128 + r) * QKPAD + seg * 8);
                CP_ASYNC16(dst, ks + base + (size_t)(kt * 128 + r) * DKV + seg * 8);
            }
        }
    };

    load_k(0, 0); CP_COMMIT();
    load_k(1, 1); CP_COMMIT();

    for (int kt = 0; kt < 16; kt++) {
        if (kt == 15) CP_WAIT0(); else CP_WAIT1();
        __syncthreads();
        const int st = kt & 1;
        __nv_bfloat16* kH = sK + (st * 2 + 0) * 128 * QKPAD;
        __nv_bfloat16* kL = sK + (st * 2 + 1) * 128 * QKPAD;

        // stage bias + key mask for this tile (256 threads: all load bias, first 128 mask)
        {
            int base_delta = kt * 128 - q0 + 1920;
            sBias[tid] = g_bias[(hh << 12) + base_delta + tid];
            if (tid < 128) sMask[tid] = g_maskf[bq * SEQ + kt * 128 + tid];
        }

        float acc[2][8][4];
#pragma unroll
        for (int mt = 0; mt < 2; mt++)
#pragma unroll
            for (int nt = 0; nt < 8; nt++)
#pragma unroll
                for (int i = 0; i < 4; i++) acc[mt][nt][i] = 0.f;

#pragma unroll
        for (int ks = 0; ks < 4; ks++) {
            int kk = ks * 16;
#pragma unroll
            for (int g = 0; g < 2; g++) {
                uint32_t bHi[4][2], bLo[4][2];
#pragma unroll
                for (int j = 0; j < 4; j++) {
                    int nt = g * 4 + j;
                    uint32_t bh2 = smem_u32(kH + (nw + nt * 8 + brow) * QKPAD + kk + bcol0);
                    LDSM_X2(bHi[j][0], bHi[j][1], bh2);
                    uint32_t bl2 = smem_u32(kL + (nw + nt * 8 + brow) * QKPAD + kk + bcol0);
                    LDSM_X2(bLo[j][0], bLo[j][1], bl2);
                }
#pragma unroll
                for (int mt = 0; mt < 2; mt++)
#pragma unroll
                    for (int j = 0; j < 4; j++) {
                        int nt = g * 4 + j;
                        mma16816(acc[mt][nt], qH[ks][mt], bHi[j]);
                        mma16816(acc[mt][nt], qH[ks][mt], bLo[j]);
                        mma16816(acc[mt][nt], qL[ks][mt], bHi[j]);
                    }
            }
        }

        __syncthreads();   // sBias/sMask visible; previous kt's sPart readers done

        // apply bias+mask, write raw scores, row tile-max
        const int r1 = mw + (lane >> 2);
        float tmax[2][2] = {{-INFINITY, -INFINITY}, {-INFINITY, -INFINITY}};
#pragma unroll
        for (int mt = 0; mt < 2; mt++) {
            int rA = r1 + mt * 16, rB = rA + 8;
            float* row0 = sp + (size_t)(q0 + rA) * SEQ + kt * 128;
            float* row1 = row0 + 8 * SEQ;
#pragma unroll
            for (int nt = 0; nt < 8; nt++) {
                int c = nw + nt * 8 + (lane & 3) * 2;
                float mk0 = sMask[c], mk1 = sMask[c + 1];
                float b0 = sBias[c - rA + 127], b1 = sBias[c + 1 - rA + 127];
                float b2 = sBias[c - rB + 127], b3 = sBias[c + 1 - rB + 127];
                acc[mt][nt][0] += b0 + mk0;  acc[mt][nt][1] += b1 + mk1;
                acc[mt][nt][2] += b2 + mk0;  acc[mt][nt][3] += b3 + mk1;
                *(float2*)&row0[c] = make_float2(acc[mt][nt][0], acc[mt][nt][1]);
                *(float2*)&row1[c] = make_float2(acc[mt][nt][2], acc[mt][nt][3]);
                tmax[mt][0] = fmaxf(tmax[mt][0], fmaxf(acc[mt][nt][0], acc[mt][nt][1]));
                tmax[mt][1] = fmaxf(tmax[mt][1], fmaxf(acc[mt][nt][2], acc[mt][nt][3]));
            }
#pragma unroll
            for (int hv = 0; hv < 2; hv++) {
                tmax[mt][hv] = fmaxf(tmax[mt][hv], __shfl_xor_sync(0xffffffffu, tmax[mt][hv], 1));
                tmax[mt][hv] = fmaxf(tmax[mt][hv], __shfl_xor_sync(0xffffffffu, tmax[mt][hv], 2));
            }
            if ((lane & 3) == 0) {
                sPart[colhalf * 128 + rA] = tmax[mt][0];
                sPart[colhalf * 128 + rB] = tmax[mt][1];
            }
        }
        __syncthreads();

        if (tid < 128) {
            float tm = fmaxf(sPart[tid], sPart[128 + tid]);
            if (kt == 0) { sMax[tid] = tm; sSum[tid] = 0.f; }
            else {
                float mo = sMax[tid];
                float mn = fmaxf(mo, tm);
                sSum[tid] *= __expf(mo - mn);
                sMax[tid] = mn;
            }
        }
        __syncthreads();

#pragma unroll
        for (int mt = 0; mt < 2; mt++) {
            int rA = r1 + mt * 16, rB = rA + 8;
            float mA = sMax[rA], mB = sMax[rB];
            float pA = 0.f, pB = 0.f;
#pragma unroll
            for (int nt = 0; nt < 8; nt++) {
                pA += __expf(acc[mt][nt][0] - mA) + __expf(acc[mt][nt][1] - mA);
                pB += __expf(acc[mt][nt][2] - mB) + __expf(acc[mt][nt][3] - mB);
            }
            pA += __shfl_xor_sync(0xffffffffu, pA, 1);
            pA += __shfl_xor_sync(0xffffffffu, pA, 2);
            pB += __shfl_xor_sync(0xffffffffu, pB, 1);
            pB += __shfl_xor_sync(0xffffffffu, pB, 2);
            if ((lane & 3) == 0) {
                sPart[colhalf * 128 + rA] = pA;
                sPart[colhalf * 128 + rB] = pB;
            }
        }
        __syncthreads();
        if (tid < 128) sSum[tid] += sPart[tid] + sPart[128 + tid];
        __syncthreads();

        if (kt + 2 < 16) { load_k(st, kt + 2); CP_COMMIT(); }
    }

    if (tid < 128)
        g_stats[(size_t)bh * SEQ + q0 + tid] = make_float2(sMax[tid], 1.0f / sSum[tid]);
}

// ---------------- ctx = softmax(scores) @ V, fused normalize + weights writeback ----------------
#define WV_W_ELE (2 * 128 * APAD)
#define WV_V_ELE (2 * 64 * APAD)
#define WV_SMEM (WV_W_ELE * 2 + 2 * WV_V_ELE * 2 + 2 * 128 * 32 * 4)

__global__ __launch_bounds__(256) void wv_mma_kernel(float* __restrict__ wts) {
    extern __shared__ char wsm_raw[];
    __nv_bfloat16* sW = (__nv_bfloat16*)wsm_raw;             // [half][128][APAD]
    __nv_bfloat16* sV = sW + WV_W_ELE;                        // [st][half][64][APAD]
    float* sWraw = (float*)(sV + 2 * WV_V_ELE);               // [st][128][32]
    __shared__ float sM[128], sInv[128];

    const int tid = threadIdx.x, wid = tid >> 5, lane = tid & 31;
    const int m0 = blockIdx.x * 128;
    const int bh = blockIdx.y;
    const int b = bh >> 4, h = bh & 15;
    float* wp = wts + (size_t)bh * SEQ * SEQ;
    const __nv_bfloat16* vh = g_vthi + (size_t)bh * DKV * SEQ;
    const __nv_bfloat16* vl = g_vtlo + (size_t)bh * DKV * SEQ;

    if (tid < 128) {
        float2 st = g_stats[(size_t)bh * SEQ + m0 + tid];
        sM[tid] = st.x;
        sInv[tid] = st.y;
    }

    const int mw = (wid & 3) * 32;
    const int nw = (wid >> 2) * 32;
    const int arow = lane & 15;
    const int acol0 = (lane >> 4) << 3;
    const int brow = lane & 7;
    const int bcol0 = ((lane >> 3) & 1) << 3;

    float acc[2][4][4];
#pragma unroll
    for (int mt = 0; mt < 2; mt++)
#pragma unroll
        for (int nt = 0; nt < 4; nt++)
#pragma unroll
            for (int i = 0; i < 4; i++) acc[mt][nt][i] = 0.f;

    auto load_stage = [&](int st, int k0) {
#pragma unroll
        for (int hh = 0; hh < 2; hh++) {
            const __nv_bfloat16* vs = hh ? vl : vh;
            int r = tid >> 2, seg = tid & 3;
            uint32_t dst = smem_u32(sV + ((st * 2 + hh) * 64 + r) * APAD + seg * 8);
            CP_ASYNC16(dst, vs + (size_t)r * SEQ + k0 + seg * 8);
        }
#pragma unroll
        for (int it = 0; it < 4; it++) {
            int i = tid + it * 256;
            int r = i >> 3, seg = i & 7;
            uint32_t dst = smem_u32(sWraw + (st * 128 + r) * 32 + seg * 4);
            CP_ASYNC16(dst, wp + (size_t)(m0 + r) * SEQ + k0 + seg * 4);
        }
    };

    load_stage(0, 0);  CP_COMMIT();
    load_stage(1, 32); CP_COMMIT();

    const int NC = SEQ / 32;
    for (int c = 0; c < NC; c++) {
        if (c == NC - 1) CP_WAIT0(); else CP_WAIT1();
        __syncthreads();
        const int st = c & 1;
        // normalize raw scores -> weights; write back (output) + hi/lo for MMA
#pragma unroll
        for (int it = 0; it < 4; it++) {
            int i = tid + it * 256;
            int r = i >> 3, seg = i & 7;
            float4 v = *(float4*)(sWraw + (st * 128 + r) * 32 + seg * 4);
            float m = sM[r], iv = sInv[r];
            v.x = __expf(v.x - m) * iv;
            v.y = __expf(v.y - m) * iv;
            v.z = __expf(v.z - m) * iv;
            v.w = __expf(v.w - m) * iv;
            *(float4*)(wp + (size_t)(m0 + r) * SEQ + c * 32 + seg * 4) = v;
            uint2 H, L;
            split2(v.x, v.y, H.x, L.x);
            split2(v.z, v.w, H.y, L.y);
            *(uint2*)(sW + r * APAD + seg * 4) = H;
            *(uint2*)(sW + (128 + r) * APAD + seg * 4) = L;
        }
        __syncthreads();

        __nv_bfloat16* vH = sV + (st * 2 + 0) * 64 * APAD;
        __nv_bfloat16* vL = sV + (st * 2 + 1) * 64 * APAD;
#pragma unroll
        for (int kk = 0; kk < 32; kk += 16) {
            uint32_t aHi[2][4], aLo[2][4], bHi[4][2], bLo[4][2];
#pragma unroll
            for (int mt = 0; mt < 2; mt++) {
                uint32_t ah = smem_u32(sW + (mw + mt * 16 + arow) * APAD + kk + acol0);
                LDSM_X4(aHi[mt][0], aHi[mt][1], aHi[mt][2], aHi[mt][3], ah);
                uint32_t al = smem_u32(sW + (128 + mw + mt * 16 + arow) * APAD + kk + acol0);
                LDSM_X4(aLo[mt][0], aLo[mt][1], aLo[mt][2], aLo[mt][3], al);
            }
#pragma unroll
            for (int nt = 0; nt < 4; nt++) {
                uint32_t bh2 = smem_u32(vH + (nw + nt * 8 + brow) * APAD + kk + bcol0);
                LDSM_X2(bHi[nt][0], bHi[nt][1], bh2);
                uint32_t bl2 = smem_u32(vL + (nw + nt * 8 + brow) * APAD + kk + bcol0);
                LDSM_X2(bLo[nt][0], bLo[nt][1], bl2);
            }
#pragma unroll
            for (int mt = 0; mt < 2; mt++)
#pragma unroll
                for (int nt = 0; nt < 4; nt++) {
                    mma16816(acc[mt][nt], aHi[mt], bHi[nt]);
                    mma16816(acc[mt][nt], aHi[mt], bLo[nt]);
                    mma16816(acc[mt][nt], aLo[mt], bHi[nt]);
                }
        }
        __syncthreads();
        if (c + 2 < NC) { load_stage(st, (c + 2) * 32); CP_COMMIT(); }
    }

#pragma unroll
    for (int mt = 0; mt < 2; mt++) {
        int s = m0 + mw + mt * 16 + (lane >> 2);
#pragma unroll
        for (int nt = 0; nt < 4; nt++) {
            int d = nw + nt * 8 + (lane & 3) * 2;
            size_t o1 = ((size_t)(b * SEQ + s)) * INNER + h * DKV + d;
            size_t o2 = ((size_t)(b * SEQ + s + 8)) * INNER + h * DKV + d;
            uint32_t hi, lo;
            split2(acc[mt][nt][0], acc[mt][nt][1], hi, lo);
            *(uint32_t*)&g_chi[o1] = hi; *(uint32_t*)&g_clo[o1] = lo;
            split2(acc[mt][nt][2], acc[mt][nt][3], hi, lo);
            *(uint32_t*)&g_chi[o2] = hi; *(uint32_t*)&g_clo[o2] = lo;
        }
    }
}

// ---------------- launch ----------------
extern "C" void kernel_launch(void* const* d_in, const int* in_sizes, int n_in,
                              void* d_out, int out_size) {
    const float* x  = (const float*)d_in[0];
    const float* Wq = (const float*)d_in[1];
    const float* bq = (const float*)d_in[2];
    const float* Wk = (const float*)d_in[3];
    const float* bk = (const float*)d_in[4];
    const float* Wv = (const float*)d_in[5];
    const float* bv = (const float*)d_in[6];
    const float* Wo = (const float*)d_in[7];
    const float* bo = (const float*)d_in[8];
    const float* rel_table = (const float*)d_in[9];
    const unsigned char* mask = (const unsigned char*)d_in[10];

    float* out = (float*)d_out;
    float* wts = out + (size_t)BSZ * SEQ * DMODEL;
    float* pb  = wts + (size_t)BSZ * NH * SEQ * SEQ;

    __nv_bfloat16 *pxhi, *pxlo, *pwhi, *pwlo, *pchi, *pclo;
    cudaGetSymbolAddress((void**)&pxhi, g_xhi);
    cudaGetSymbolAddress((void**)&pxlo, g_xlo);
    cudaGetSymbolAddress((void**)&pwhi, g_whi);
    cudaGetSymbolAddress((void**)&pwlo, g_wlo);
    cudaGetSymbolAddress((void**)&pchi, g_chi);
    cudaGetSymbolAddress((void**)&pclo, g_clo);

    cudaFuncSetAttribute(mma_gemm_kernel,
                         cudaFuncAttributeMaxDynamicSharedMemorySize, GEMM_SMEM);
    cudaFuncSetAttribute(qk_mma_kernel,
                         cudaFuncAttributeMaxDynamicSharedMemorySize, QK_SMEM);
    cudaFuncSetAttribute(wv_mma_kernel,
                         cudaFuncAttributeMaxDynamicSharedMemorySize, WV_SMEM);

    const size_t WSTRIDE = (size_t)DMODEL * INNER;

    // launch 1: all preprocessing
    prep_kernel<<<NCVT + NTRANS + 256 + 1, 256>>>(x, Wq, Wk, Wv, Wo, rel_table, mask);

    // launch 2: fused QKV projection (N = 3072)
    mma_gemm_kernel<<<dim3(3 * INNER / 64, MTOT / 128), 256, GEMM_SMEM>>>(
        pxhi, pxlo, pwhi, pwlo, bq, bk, bv, nullptr, 1);

    // launch 3: pos_bias output
    posbias_kernel<<<(NH * (size_t)SEQ * SEQ) / 256, 256>>>(pb);

    // launch 4: scores + fused softmax stats  (ncu capture target)
    qk_mma_kernel<<<dim3(SEQ / 128, BSZ * NH), 256, QK_SMEM>>>(wts);

    // launch 5: normalize + weights writeback + ctx
    wv_mma_kernel<<<dim3(SEQ / 128, BSZ * NH), 256, WV_SMEM>>>(wts);

    // launch 6: output projection
    mma_gemm_kernel<<<dim3(INNER / 64, MTOT / 128), 256, GEMM_SMEM>>>(
        pchi, pclo, pwhi + 3 * WSTRIDE, pwlo + 3 * WSTRIDE, bo, bo, bo, out, 0);
}